// round 6
// baseline (speedup 1.0000x reference)
#include <cuda_runtime.h>

#define TT 20
#define MM 6
#define MAXN 8192
typedef unsigned long long u64;

// scratch (allocation-free rule: __device__ globals)
__device__ __align__(16) float g_hidden[(size_t)TT * MAXN * MM * 12];
__device__ __align__(16) float g_lstm[2][(size_t)TT * MAXN * MM * 12];

// ---------------- f32x2 helpers ----------------
__device__ __forceinline__ u64 pk(float a, float b) {
    u64 r; asm("mov.b64 %0, {%1, %2};" : "=l"(r) : "f"(a), "f"(b)); return r;
}
__device__ __forceinline__ void upk(float& a, float& b, u64 v) {
    asm("mov.b64 {%0, %1}, %2;" : "=f"(a), "=f"(b) : "l"(v));
}
__device__ __forceinline__ u64 ffma2(u64 a, u64 b, u64 c) {
    u64 r; asm("fma.rn.f32x2 %0, %1, %2, %3;" : "=l"(r) : "l"(a), "l"(b), "l"(c)); return r;
}
__device__ __forceinline__ u64 fadd2(u64 a, u64 b) {
    u64 r; asm("add.rn.f32x2 %0, %1, %2;" : "=l"(r) : "l"(a), "l"(b)); return r;
}

// packed 9-dot: W[0..8] (pairs), v[0..8] (pairs)
__device__ __forceinline__ u64 dotp9(const u64* __restrict__ W, const u64* v, u64 acc) {
    #pragma unroll
    for (int kk = 0; kk < 4; kk++) {
        ulonglong2 w = *(const ulonglong2*)(W + 2*kk);
        acc = ffma2(w.x, v[2*kk],   acc);
        acc = ffma2(w.y, v[2*kk+1], acc);
    }
    acc = ffma2(W[8], v[8], acc);
    return acc;
}
// packed 18-dot with split (tree) accumulation: two parallel 9-chains + 1 add
__device__ __forceinline__ u64 dotp18(const u64* __restrict__ W, const u64* va, const u64* vb, u64 acc) {
    u64 a1 = dotp9(W, va, acc);
    u64 a2 = dotp9(W + 10, vb, 0ull);
    return fadd2(a1, a2);
}

// ---------------- MUFU activations ----------------
__device__ __forceinline__ float fsig(float x) {
    float e, r;
    asm("ex2.approx.f32 %0, %1;" : "=f"(e) : "f"(x * -1.4426950408889634f));
    asm("rcp.approx.f32 %0, %1;" : "=f"(r) : "f"(1.0f + e));
    return r;
}
__device__ __forceinline__ float ftanh_(float x) {
    float e, r;
    asm("ex2.approx.f32 %0, %1;" : "=f"(e) : "f"(x * -2.8853900817779268f));
    asm("rcp.approx.f32 %0, %1;" : "=f"(r) : "f"(1.0f + e));
    return fmaf(2.0f, r, -1.0f);
}

// ---------------- scalar dot helpers ----------------
__device__ __forceinline__ float dot9(const float* __restrict__ w, const float* r) {
    float4 a = *(const float4*)w;
    float4 b = *(const float4*)(w + 4);
    float acc = w[8] * r[8];
    acc = fmaf(a.x, r[0], acc); acc = fmaf(a.y, r[1], acc);
    acc = fmaf(a.z, r[2], acc); acc = fmaf(a.w, r[3], acc);
    acc = fmaf(b.x, r[4], acc); acc = fmaf(b.y, r[5], acc);
    acc = fmaf(b.z, r[6], acc); acc = fmaf(b.w, r[7], acc);
    return acc;
}
__device__ __forceinline__ void load9(float* r, const float* __restrict__ p) {
    float4 a = *(const float4*)p;
    float4 b = *(const float4*)(p + 4);
    r[0]=a.x; r[1]=a.y; r[2]=a.z; r[3]=a.w;
    r[4]=b.x; r[5]=b.y; r[6]=b.z; r[7]=b.w;
    r[8]=p[8];
}
__device__ __forceinline__ void store9(float* __restrict__ p, const float* r) {
    *(float4*)p       = make_float4(r[0], r[1], r[2], r[3]);
    *(float4*)(p + 4) = make_float4(r[4], r[5], r[6], r[7]);
    p[8] = r[8];
}

// ================= K1: GRU message passing + p0 readout =================
__global__ __launch_bounds__(192)
void k1_gru(const float* __restrict__ nf, const float* __restrict__ pos,
            const float* __restrict__ attm,
            const float* __restrict__ msgW, const float* __restrict__ msgb,
            const float* __restrict__ gWih, const float* __restrict__ gWhh,
            const float* __restrict__ gbih, const float* __restrict__ gbhh,
            const float* __restrict__ ro1W, const float* __restrict__ ro1b,
            const float* __restrict__ ro2W, const float* __restrict__ ro2b,
            const int* __restrict__ numrec, float* __restrict__ out_p0, int N)
{
    __shared__ __align__(16) u64 s_PM[4][10];     // msg rows (2p,2p+1) packed
    __shared__ __align__(16) u64 s_P1[9][20];     // [0..8] Wih(d,9+d), [10..18] Whh(d,9+d)
    __shared__ __align__(16) u64 s_P3[9][10];     // (Wih[18+d], Whh[18+d]) packed
    __shared__ __align__(16) u64 s_bA[9], s_b3[9], s_bm[4];
    __shared__ __align__(16) float s_msgW8[12], s_ro1W[9*12], s_ro2W[7*12];
    __shared__ __align__(16) float s_ro1b[12], s_ro2b[8];
    __shared__ float s_bm8;
    __shared__ __align__(16) float s_msg[192*12];

    const int tid = threadIdx.x;
    // ---- staging (pre-packed weights) ----
    for (int i = tid; i < 36; i += 192) {
        int p = i/9, k = i%9;
        ((float2*)s_PM)[p*10 + k] = make_float2(msgW[(2*p)*9 + k], msgW[(2*p+1)*9 + k]);
    }
    for (int i = tid; i < 162; i += 192) {
        int d = i/18, k = i%18;
        float lo, hi; int idx;
        if (k < 9) { lo = gWih[d*9+k];        hi = gWih[(9+d)*9+k];        idx = d*20 + k; }
        else { int kk = k-9; lo = gWhh[d*9+kk]; hi = gWhh[(9+d)*9+kk];     idx = d*20 + 10 + kk; }
        ((float2*)s_P1)[idx] = make_float2(lo, hi);
    }
    for (int i = tid; i < 81; i += 192) {
        int d = i/9, k = i%9;
        ((float2*)s_P3)[d*10 + k] = make_float2(gWih[(18+d)*9+k], gWhh[(18+d)*9+k]);
    }
    if (tid < 4) ((float2*)s_bm)[tid] = make_float2(msgb[2*tid], msgb[2*tid+1]);
    if (tid == 4) s_bm8 = msgb[8];
    if (tid < 9) {
        ((float2*)s_bA)[tid] = make_float2(gbih[tid] + gbhh[tid], gbih[9+tid] + gbhh[9+tid]);
        ((float2*)s_b3)[tid] = make_float2(gbih[18+tid], gbhh[18+tid]);
        s_msgW8[tid] = msgW[8*9 + tid];
        s_ro1b[tid] = ro1b[tid];
    }
    for (int i = tid; i < 81; i += 192) s_ro1W[(i/9)*12 + i%9] = ro1W[i];
    for (int i = tid; i < 63; i += 192) s_ro2W[(i/9)*12 + i%9] = ro2W[i];
    if (tid < 7) s_ro2b[tid] = ro2b[tid];

    const int g = tid / 6, m = tid % 6;
    const int ntot = N * TT;
    int nt = blockIdx.x * 32 + g;
    const bool vnt = nt < ntot;
    if (!vnt) nt = 0;
    const int n = nt / TT, t = nt % TT;
    const int nr0 = numrec[(size_t)n * TT];
    const float vm = (m < nr0) ? 1.0f : 0.0f;

    float h[9], attr[6];
    {
        const float* q = nf + (size_t)nt*18 + m*3;
        h[0]=q[0]; h[1]=q[1]; h[2]=q[2];
        const float* pq = pos + (size_t)nt*36 + m*6;
        #pragma unroll
        for (int j = 0; j < 6; j++) h[3+j] = pq[j];
        const float* aq = attm + (size_t)nt*36 + m*6;
        #pragma unroll
        for (int j = 0; j < 6; j++) attr[j] = (j < nr0) ? aq[j] : 0.0f;
    }
    u64 a2[6];
    #pragma unroll
    for (int j = 0; j < 6; j++) a2[j] = pk(attr[j], attr[j]);
    __syncthreads();

    #pragma unroll
    for (int rd = 0; rd < 2; rd++) {
        u64 hd2[9];
        #pragma unroll
        for (int k = 0; k < 9; k++) hd2[k] = pk(h[k], h[k]);
        // msg = W_msg h + b  (4 packed row-pairs + row 8 scalar)
        float msg[9];
        #pragma unroll
        for (int p = 0; p < 4; p++) {
            u64 acc = dotp9(&s_PM[p][0], hd2, s_bm[p]);
            upk(msg[2*p], msg[2*p+1], acc);
        }
        msg[8] = s_bm8 + dot9(s_msgW8, h);
        store9(s_msg + tid*12, msg);
        __syncthreads();
        // mg = sum_j att_j * msg_j   (packed pairs)
        u64 mgp[4] = {0,0,0,0};
        float mg8 = 0.0f;
        #pragma unroll
        for (int j = 0; j < 6; j++) {
            const float* mp = s_msg + (g*6 + j)*12;
            const u64* mpp = (const u64*)mp;
            mgp[0] = ffma2(a2[j], mpp[0], mgp[0]);
            mgp[1] = ffma2(a2[j], mpp[1], mgp[1]);
            mgp[2] = ffma2(a2[j], mpp[2], mgp[2]);
            mgp[3] = ffma2(a2[j], mpp[3], mgp[3]);
            mg8 = fmaf(attr[j], mp[8], mg8);
        }
        float mg[9];
        #pragma unroll
        for (int p = 0; p < 4; p++) upk(mg[2*p], mg[2*p+1], mgp[p]);
        mg[8] = mg8;
        u64 mg2[9], mh2[9];
        #pragma unroll
        for (int k = 0; k < 9; k++) { mg2[k] = pk(mg[k], mg[k]); mh2[k] = pk(mg[k], h[k]); }
        // GRU cell
        float hn[9];
        #pragma unroll
        for (int d = 0; d < 9; d++) {
            u64 acc1 = dotp18(&s_P1[d][0], mg2, hd2, s_bA[d]);   // (r_pre, z_pre)
            u64 acc3 = dotp9(&s_P3[d][0], mh2, s_b3[d]);         // (gx2, gh2)
            float a0, a1, gx2, gh2;
            upk(a0, a1, acc1);
            upk(gx2, gh2, acc3);
            float r  = fsig(a0);
            float z  = fsig(a1);
            float nn = ftanh_(fmaf(r, gh2, gx2));
            hn[d] = fmaf(z, h[d] - nn, nn) * vm;
        }
        #pragma unroll
        for (int d = 0; d < 9; d++) h[d] = hn[d];
        __syncthreads();
    }

    if (vnt) {
        store9(g_hidden + ((size_t)t * (N*MM) + n*MM + m) * 12, h);
        float q[9];
        #pragma unroll
        for (int d = 0; d < 9; d++)
            q[d] = fmaxf(s_ro1b[d] + dot9(s_ro1W + d*12, h), 0.0f);
        float* po = out_p0 + ((size_t)n*(TT*MM) + t*MM + m) * 7;
        #pragma unroll
        for (int k = 0; k < 7; k++)
            po[k] = (s_ro2b[k] + dot9(s_ro2W + k*12, q)) * vm;
    }
}

// ================= K2: Bi-LSTM, thread = one chain (n,m,dir) =================
__global__ __launch_bounds__(256, 2)
void k2_lstm(const float* __restrict__ lfWih, const float* __restrict__ lfWhh,
             const float* __restrict__ lfbih, const float* __restrict__ lfbhh,
             const float* __restrict__ lbWih, const float* __restrict__ lbWhh,
             const float* __restrict__ lbbih, const float* __restrict__ lbbhh,
             int N)
{
    // per dirn, per d: [0..8] Wi rows (d,9+d) packed; [10..18] Wh rows (d,9+d)
    __shared__ __align__(16) u64 s_WA[2][9][20];  // gates (i,f)
    __shared__ __align__(16) u64 s_WB[2][9][20];  // gates (g,o)
    __shared__ __align__(16) u64 s_bA2[18], s_bB2[18];

    const int tid = threadIdx.x;
    for (int i = tid; i < 324; i += 256) {
        int dirn = i / 162, r = i % 162, d = r/18, k = r%18;
        const float* Wi = dirn ? lbWih : lfWih;
        const float* Wh = dirn ? lbWhh : lfWhh;
        float loA, hiA, loB, hiB; int idx;
        if (k < 9) {
            loA = Wi[d*9+k];      hiA = Wi[(9+d)*9+k];
            loB = Wi[(18+d)*9+k]; hiB = Wi[(27+d)*9+k];
            idx = k;
        } else {
            int kk = k - 9;
            loA = Wh[d*9+kk];      hiA = Wh[(9+d)*9+kk];
            loB = Wh[(18+d)*9+kk]; hiB = Wh[(27+d)*9+kk];
            idx = 10 + kk;
        }
        ((float2*)&s_WA[dirn][d][0])[idx] = make_float2(loA, hiA);
        ((float2*)&s_WB[dirn][d][0])[idx] = make_float2(loB, hiB);
    }
    if (tid < 18) {
        int dirn = tid / 9, d = tid % 9;
        const float* bi = dirn ? lbbih : lfbih;
        const float* bh = dirn ? lbbhh : lfbhh;
        ((float2*)s_bA2)[tid] = make_float2(bi[d] + bh[d],       bi[9+d] + bh[9+d]);
        ((float2*)s_bB2)[tid] = make_float2(bi[18+d] + bh[18+d], bi[27+d] + bh[27+d]);
    }
    __syncthreads();

    const int half = N * MM;
    const int cid = blockIdx.x * 256 + tid;
    if (cid >= 2*half) return;
    const int dirn = (cid >= half) ? 1 : 0;   // warp-uniform (half % 256 == 0)
    const int nm = cid - dirn*half;

    const u64* WA = &s_WA[dirn][0][0];
    const u64* WB = &s_WB[dirn][0][0];
    const u64* bA = s_bA2 + dirn*9;
    const u64* bB = s_bB2 + dirn*9;

    float h[9], c[9];
    #pragma unroll
    for (int d = 0; d < 9; d++) { h[d] = 0.0f; c[d] = 0.0f; }

    const long  tstep = (long)half * 12;
    const long  sstep = dirn ? -tstep : tstep;
    const float* xp = g_hidden + (size_t)nm*12 + (dirn ? (size_t)(TT-1)*tstep : 0);
    float*       op = g_lstm[dirn] + (size_t)nm*12 + (dirn ? (size_t)(TT-1)*tstep : 0);

    float x[9];
    load9(x, xp);
    for (int s = 0; s < TT; s++) {
        xp += sstep;
        float xn[9];
        if (s < TT-1) load9(xn, xp);      // prefetch next step's input
        u64 xx[9], hh[9];
        #pragma unroll
        for (int k = 0; k < 9; k++) { xx[k] = pk(x[k], x[k]); hh[k] = pk(h[k], h[k]); }
        #pragma unroll
        for (int d = 0; d < 9; d++) {
            u64 accA = dotp18(WA + d*20, xx, hh, bA[d]);   // (i_pre, f_pre)
            u64 accB = dotp18(WB + d*20, xx, hh, bB[d]);   // (g_pre, o_pre)
            float gi, gf, gG, go;
            upk(gi, gf, accA);
            upk(gG, go, accB);
            float i_ = fsig(gi);
            float f_ = fsig(gf);
            float gg = ftanh_(gG);
            float o_ = fsig(go);
            c[d] = fmaf(f_, c[d], i_ * gg);
            h[d] = o_ * ftanh_(c[d]);      // safe: hh already packed
        }
        store9(op, h);
        op += sstep;
        #pragma unroll
        for (int d = 0; d < 9; d++) x[d] = xn[d];
    }
}

// ================= K3: final readout p =================
__global__ __launch_bounds__(256)
void k3_readout(const float* __restrict__ lr1W, const float* __restrict__ lr1b,
                const float* __restrict__ lr2W, const float* __restrict__ lr2b,
                const int* __restrict__ numrec, float* __restrict__ out_p, int N)
{
    __shared__ __align__(16) u64 s_R1[4][20];      // lr1 row pairs (2p,2p+1), 18 cols
    __shared__ __align__(16) u64 s_R1b[4];
    __shared__ __align__(16) u64 s_R2[3][10];      // lr2 row pairs, 9 cols
    __shared__ __align__(16) u64 s_R2b[3];
    __shared__ __align__(16) float s_R1s[20], s_R2s[12];  // scalar rows 8 / 6
    __shared__ float s_R1bs, s_R2bs;

    const int tid = threadIdx.x;
    for (int i = tid; i < 72; i += 256) {
        int p = i/18, k = i%18;
        ((float2*)&s_R1[p][0])[k] = make_float2(lr1W[(2*p)*18+k], lr1W[(2*p+1)*18+k]);
    }
    if (tid < 18) s_R1s[tid] = lr1W[8*18 + tid];
    for (int i = tid; i < 27; i += 256) {
        int p = i/9, k = i%9;
        ((float2*)&s_R2[p][0])[k] = make_float2(lr2W[(2*p)*9+k], lr2W[(2*p+1)*9+k]);
    }
    if (tid < 9) s_R2s[tid] = lr2W[6*9 + tid];
    if (tid < 4) ((float2*)s_R1b)[tid] = make_float2(lr1b[2*tid], lr1b[2*tid+1]);
    if (tid == 4) s_R1bs = lr1b[8];
    if (tid < 3) ((float2*)s_R2b)[tid] = make_float2(lr2b[2*tid], lr2b[2*tid+1]);
    if (tid == 3) s_R2bs = lr2b[6];
    __syncthreads();

    const int half = N * MM;
    const int id = blockIdx.x * 256 + tid;
    if (id >= TT * half) return;
    const int t = id / half;
    const int nm = id - t * half;

    float o18[18];
    load9(o18,     g_lstm[0] + ((size_t)t*half + nm)*12);
    load9(o18 + 9, g_lstm[1] + ((size_t)t*half + nm)*12);
    u64 o2[18];
    #pragma unroll
    for (int k = 0; k < 18; k++) o2[k] = pk(o18[k], o18[k]);

    float q[9];
    #pragma unroll
    for (int p = 0; p < 4; p++) {
        u64 acc = s_R1b[p];
        #pragma unroll
        for (int k = 0; k < 18; k++) acc = ffma2(s_R1[p][k], o2[k], acc);
        float a, b; upk(a, b, acc);
        q[2*p]   = fmaxf(a, 0.0f);
        q[2*p+1] = fmaxf(b, 0.0f);
    }
    {
        float acc = s_R1bs;
        #pragma unroll
        for (int k = 0; k < 18; k++) acc = fmaf(s_R1s[k], o18[k], acc);
        q[8] = fmaxf(acc, 0.0f);
    }
    u64 q2[9];
    #pragma unroll
    for (int k = 0; k < 9; k++) q2[k] = pk(q[k], q[k]);

    float o7[7];
    #pragma unroll
    for (int p = 0; p < 3; p++) {
        u64 acc = s_R2b[p];
        #pragma unroll
        for (int k = 0; k < 9; k++) acc = ffma2(s_R2[p][k], q2[k], acc);
        upk(o7[2*p], o7[2*p+1], acc);
    }
    {
        float acc = s_R2bs;
        #pragma unroll
        for (int k = 0; k < 9; k++) acc = fmaf(s_R2s[k], q[k], acc);
        o7[6] = acc;
    }

    const int n = nm / MM, m = nm - n*MM;
    const int nr0 = numrec[(size_t)n * TT];
    const float vm = (m < nr0) ? 1.0f : 0.0f;
    float* po = out_p + ((size_t)n*(TT*MM) + t*MM + m) * 7;
    #pragma unroll
    for (int k = 0; k < 7; k++) po[k] = o7[k] * vm;
}

extern "C" void kernel_launch(void* const* d_in, const int* in_sizes, int n_in,
                              void* d_out, int out_size)
{
    const float* nf    = (const float*)d_in[0];
    const float* pos   = (const float*)d_in[1];
    const float* attm  = (const float*)d_in[2];
    const float* msgW  = (const float*)d_in[3];
    const float* msgb  = (const float*)d_in[4];
    const float* gWih  = (const float*)d_in[5];
    const float* gWhh  = (const float*)d_in[6];
    const float* gbih  = (const float*)d_in[7];
    const float* gbhh  = (const float*)d_in[8];
    const float* ro1W  = (const float*)d_in[9];
    const float* ro1b  = (const float*)d_in[10];
    const float* ro2W  = (const float*)d_in[11];
    const float* ro2b  = (const float*)d_in[12];
    const float* lfWih = (const float*)d_in[13];
    const float* lfWhh = (const float*)d_in[14];
    const float* lfbih = (const float*)d_in[15];
    const float* lfbhh = (const float*)d_in[16];
    const float* lbWih = (const float*)d_in[17];
    const float* lbWhh = (const float*)d_in[18];
    const float* lbbih = (const float*)d_in[19];
    const float* lbbhh = (const float*)d_in[20];
    const float* lr1W  = (const float*)d_in[21];
    const float* lr1b  = (const float*)d_in[22];
    const float* lr2W  = (const float*)d_in[23];
    const float* lr2b  = (const float*)d_in[24];
    const int*   nrec  = (const int*)d_in[25];

    const int N = in_sizes[25] / TT;
    float* out = (float*)d_out;
    float* out_p  = out;                              // pred_label
    float* out_p0 = out + (size_t)N * TT * MM * 7;    // pred_label0

    const int grid1 = (N*TT + 31) / 32;
    const int grid2 = (N*MM*2 + 255) / 256;
    const int grid3 = (N*TT*MM + 255) / 256;

    k1_gru<<<grid1, 192>>>(nf, pos, attm, msgW, msgb, gWih, gWhh, gbih, gbhh,
                           ro1W, ro1b, ro2W, ro2b, nrec, out_p0, N);
    k2_lstm<<<grid2, 256>>>(lfWih, lfWhh, lfbih, lfbhh,
                            lbWih, lbWhh, lbbih, lbbhh, N);
    k3_readout<<<grid3, 256>>>(lr1W, lr1b, lr2W, lr2b, nrec, out_p, N);
}